// round 10
// baseline (speedup 1.0000x reference)
#include <cuda_runtime.h>
#include <cuda_bf16.h>
#include <cstdint>

#define NNODES 20000
#define CH 256
#define ECH 64
#define MAXE 320000

typedef unsigned long long ull;

// ---------------- scratch (__device__ globals; no allocation) ----------------
__device__ float g_agg[NNODES * CH];          // fp32 aggregation target (self-cleaned)
__device__ float g_h[NNODES * CH];
__device__ int   g_cnt[NNODES];               // self-cleaned by scan
__device__ int   g_rowstart[NNODES + 1];
__device__ int   g_cursor[NNODES];
__device__ int4  g_csr4[MAXE];                // {eid, src, dst, 0}, dst-sorted
__device__ float g_sum[CH];                   // self-cleaned by agg_split
__device__ float g_sumsq[CH];
__device__ __align__(16) __nv_bfloat16 g_x_hi[NNODES * CH], g_x_lo[NNODES * CH];
__device__ __align__(16) __nv_bfloat16 g_agg_hi[NNODES * CH], g_agg_lo[NNODES * CH];
__device__ __align__(16) __nv_bfloat16 g_WTe_hi[CH * ECH], g_WTe_lo[CH * ECH];
__device__ __align__(16) __nv_bfloat16 g_WTrel_hi[CH * CH], g_WTrel_lo[CH * CH];
__device__ __align__(16) __nv_bfloat16 g_WTroot_hi[CH * CH], g_WTroot_lo[CH * CH];
__device__ __align__(16) __nv_bfloat16 g_WTres_hi[CH * CH], g_WTres_lo[CH * CH];

// ---------------- helpers ----------------
__device__ __forceinline__ uint32_t smem_u32(const void* p) {
    uint32_t a;
    asm("{ .reg .u64 t; cvta.to.shared.u64 t, %1; cvt.u32.u64 %0, t; }" : "=r"(a) : "l"(p));
    return a;
}
#define SWZ(off) ((off) ^ (((off) >> 3) & 0x70))

__device__ __forceinline__ void cpa16(uint32_t dst, const void* src, int pred16) {
    asm volatile("cp.async.cg.shared.global [%0], [%1], 16, %2;"
                 :: "r"(dst), "l"(src), "r"(pred16 ? 16 : 0) : "memory");
}
#define CP_COMMIT() asm volatile("cp.async.commit_group;" ::: "memory")
#define CP_WAIT(n)  asm volatile("cp.async.wait_group %0;" :: "n"(n) : "memory")

__device__ __forceinline__ void ldsm_x4(uint32_t* r, uint32_t addr) {
    asm volatile("ldmatrix.sync.aligned.m8n8.x4.shared.b16 {%0,%1,%2,%3}, [%4];"
        : "=r"(r[0]), "=r"(r[1]), "=r"(r[2]), "=r"(r[3]) : "r"(addr));
}
__device__ __forceinline__ void ldsm_x2(uint32_t* r, uint32_t addr) {
    asm volatile("ldmatrix.sync.aligned.m8n8.x2.shared.b16 {%0,%1}, [%2];"
        : "=r"(r[0]), "=r"(r[1]) : "r"(addr));
}
__device__ __forceinline__ void mma16816(float* c, const uint32_t* a, const uint32_t* b) {
    asm volatile("mma.sync.aligned.m16n8k16.row.col.f32.bf16.bf16.f32 "
        "{%0,%1,%2,%3}, {%4,%5,%6,%7}, {%8,%9}, {%0,%1,%2,%3};"
        : "+f"(c[0]), "+f"(c[1]), "+f"(c[2]), "+f"(c[3])
        : "r"(a[0]), "r"(a[1]), "r"(a[2]), "r"(a[3]), "r"(b[0]), "r"(b[1]));
}
__device__ __forceinline__ void split4(float4 v, ull& hb, ull& lb) {
    __nv_bfloat16 h0 = __float2bfloat16(v.x), h1 = __float2bfloat16(v.y);
    __nv_bfloat16 h2 = __float2bfloat16(v.z), h3 = __float2bfloat16(v.w);
    __nv_bfloat16 l0 = __float2bfloat16(v.x - __bfloat162float(h0));
    __nv_bfloat16 l1 = __float2bfloat16(v.y - __bfloat162float(h1));
    __nv_bfloat16 l2 = __float2bfloat16(v.z - __bfloat162float(h2));
    __nv_bfloat16 l3 = __float2bfloat16(v.w - __bfloat162float(h3));
    hb = (ull)__bfloat16_as_ushort(h0) | ((ull)__bfloat16_as_ushort(h1) << 16) |
         ((ull)__bfloat16_as_ushort(h2) << 32) | ((ull)__bfloat16_as_ushort(h3) << 48);
    lb = (ull)__bfloat16_as_ushort(l0) | ((ull)__bfloat16_as_ushort(l1) << 16) |
         ((ull)__bfloat16_as_ushort(l2) << 32) | ((ull)__bfloat16_as_ushort(l3) << 48);
}

// ---------------------------------------------------------------------------
// K1: hist + weight prep + x split (disjoint block ranges)
// ---------------------------------------------------------------------------
__global__ void __launch_bounds__(256) hist_prep(
    const int* __restrict__ ei,
    const float* __restrict__ We, const float* __restrict__ Wrel,
    const float* __restrict__ Wroot, const float* __restrict__ Wres,
    const float* __restrict__ x, int E, int nh)
{
    int b = blockIdx.x;
    int t = threadIdx.x;
    if (b < nh) {
        int e = b * 256 + t;
        if (e < E) atomicAdd(&g_cnt[__ldg(&ei[E + e])], 1);
    } else if (b < nh + 256) {
        int n = b - nh, k = t;
        if (k < ECH) {
            float v = __ldg(&We[(size_t)k * CH + n]);
            __nv_bfloat16 h = __float2bfloat16(v);
            g_WTe_hi[n * ECH + k] = h;
            g_WTe_lo[n * ECH + k] = __float2bfloat16(v - __bfloat162float(h));
        }
        {
            float v = __ldg(&Wrel[(size_t)k * CH + n]);
            __nv_bfloat16 h = __float2bfloat16(v);
            g_WTrel_hi[n * CH + k] = h;
            g_WTrel_lo[n * CH + k] = __float2bfloat16(v - __bfloat162float(h));
        }
        {
            float v = __ldg(&Wroot[(size_t)k * CH + n]);
            __nv_bfloat16 h = __float2bfloat16(v);
            g_WTroot_hi[n * CH + k] = h;
            g_WTroot_lo[n * CH + k] = __float2bfloat16(v - __bfloat162float(h));
        }
        {
            float v = __ldg(&Wres[(size_t)k * CH + n]);
            __nv_bfloat16 h = __float2bfloat16(v);
            g_WTres_hi[n * CH + k] = h;
            g_WTres_lo[n * CH + k] = __float2bfloat16(v - __bfloat162float(h));
        }
    } else {
        const int total = NNODES * CH / 4;
        int idx = (b - nh - 256) * 256 + t;
        int stride = (gridDim.x - nh - 256) * 256;
        for (int i = idx; i < total; i += stride) {
            float4 v = __ldg(((const float4*)x) + i);
            ull hb, lb; split4(v, hb, lb);
            ((ull*)g_x_hi)[i] = hb;
            ((ull*)g_x_lo)[i] = lb;
        }
    }
}

// ---------------------------------------------------------------------------
// K2: scan (reads g_cnt, zeroes it for the next replay)
// ---------------------------------------------------------------------------
__global__ void __launch_bounds__(1024) scan_kernel(int E) {
    __shared__ int sp[1024];
    const int t = threadIdx.x;
    const int CHUNK = (NNODES + 1023) / 1024;
    int beg = t * CHUNK;
    int end = min(beg + CHUNK, NNODES);
    int mysum = 0;
    for (int i = beg; i < end; i++) mysum += g_cnt[i];
    sp[t] = mysum;
    __syncthreads();
#pragma unroll
    for (int off = 1; off < 1024; off <<= 1) {
        int v = (t >= off) ? sp[t - off] : 0;
        __syncthreads();
        sp[t] += v;
        __syncthreads();
    }
    int running = sp[t] - mysum;
    for (int i = beg; i < end; i++) {
        int c = g_cnt[i];
        g_cnt[i] = 0;               // self-clean for next replay
        g_rowstart[i] = running;
        g_cursor[i] = running;
        running += c;
    }
    if (t == 1023) g_rowstart[NNODES] = E;
}

// ---------------------------------------------------------------------------
// K3: fill CSR as int4 {eid, src, dst, 0}
// ---------------------------------------------------------------------------
__global__ void fill_kernel(const int* __restrict__ ei, int E) {
    int e = blockIdx.x * blockDim.x + threadIdx.x;
    if (e < E) {
        int dst = __ldg(&ei[E + e]);
        int src = __ldg(&ei[e]);
        int pos = atomicAdd(&g_cursor[dst], 1);
        g_csr4[pos] = make_int4(e, src, dst, 0);
    }
}

// ---------------------------------------------------------------------------
// K4 (profiled): fused edge GEMM + message + aggregation.
// MMA as before. Epilogue v2.1: stage fp32 acc into (dead) A/B smem as
// [128 edge][128 ch] chunks (row stride 130 words), then dst-major reduce:
// thread = (channel, edge-quarter); coalesced x reads, no shfls, per-segment
// red.global.add.f32. Masks force a flush at every quarter end (i==31) —
// cross-quarter segments resolve via the atomic adds (R9 bug fix).
// smem: Ah 16K | Al 16K | Bh 32K | Bl 32K | csr 2K | masks
// ---------------------------------------------------------------------------
__global__ void __launch_bounds__(512, 2) egemm_fused(
    const float* __restrict__ ea, const float* __restrict__ x, int E)
{
    extern __shared__ char dsm[];
    char* base = (char*)(((uintptr_t)dsm + 1023) & ~(uintptr_t)1023);
    char* Ah = base;
    char* Al = base + 16384;
    char* Bh = base + 32768;
    char* Bl = base + 65536;
    int4* s_csr = (int4*)(base + 98304);
    unsigned* s_mask = (unsigned*)(base + 98304 + 2048);
    float* stage = (float*)base;               // reuses A/B region after MMA
    const int SROW = 130;                      // words per staged row (float2-aligned)

    const int tid = threadIdx.x;
    const int lane = tid & 31;
    const int wid = tid >> 5;
    const int wm = wid >> 3;     // 0..1
    const int wn = wid & 7;      // 0..7
    const int m0 = blockIdx.x * 128;

    // stage CSR tile
    if (tid < 128) {
        int r = m0 + tid;
        s_csr[tid] = (r < E) ? __ldg(&g_csr4[r]) : make_int4(0, 0, -1, 0);
    }
    __syncthreads();

    // segment "last" masks per 32-edge quarter; ALWAYS flush at quarter end
    if (tid < 4) {
        unsigned m = 0;
        for (int i = 0; i < 32; i++) {
            int e = tid * 32 + i;
            bool last = (i == 31) || (s_csr[e + 1].z != s_csr[e].z);
            m |= (last ? 1u : 0u) << i;
        }
        s_mask[tid] = m;
    }

    // A: gather ea rows in CSR order, split fp32 -> hi/lo bf16
    for (int idx = tid; idx < 2048; idx += 512) {
        int row = idx >> 4, q = idx & 15;
        int4 cs = s_csr[row];
        float4 v = make_float4(0.f, 0.f, 0.f, 0.f);
        if (cs.z >= 0) v = __ldg((const float4*)(ea + (size_t)cs.x * ECH) + q);
        ull hb, lb; split4(v, hb, lb);
        uint32_t off = SWZ(row * 128 + q * 8);
        *(ull*)(Ah + off) = hb;
        *(ull*)(Al + off) = lb;
    }
    // B: WTe 256 x 64 bf16 hi/lo
    {
        const uint4* sh = (const uint4*)g_WTe_hi;
        const uint4* sl = (const uint4*)g_WTe_lo;
        for (int idx = tid; idx < 2048; idx += 512) {
            int n = idx >> 3, q = idx & 7;
            uint32_t off = SWZ(n * 128 + q * 16);
            *(uint4*)(Bh + off) = __ldg(&sh[idx]);
            *(uint4*)(Bl + off) = __ldg(&sl[idx]);
        }
    }
    __syncthreads();

    float acc[4][4][4];
#pragma unroll
    for (int i = 0; i < 4; i++)
#pragma unroll
        for (int j = 0; j < 4; j++)
#pragma unroll
            for (int k = 0; k < 4; k++) acc[i][j][k] = 0.f;

    const uint32_t ah = smem_u32(Ah), al = smem_u32(Al);
    const uint32_t bh = smem_u32(Bh), bl = smem_u32(Bl);

#pragma unroll
    for (int ks = 0; ks < 4; ks++) {
        int ko = ks * 32;
        uint32_t afh[4][4], afl[4][4];
#pragma unroll
        for (int i = 0; i < 4; i++) {
            uint32_t aoff = SWZ((wm * 64 + i * 16 + (lane & 15)) * 128 + ko + (lane >> 4) * 16);
            ldsm_x4(afh[i], ah + aoff);
            ldsm_x4(afl[i], al + aoff);
        }
#pragma unroll
        for (int j = 0; j < 4; j++) {
            uint32_t boff = SWZ((wn * 32 + j * 8 + (lane & 7)) * 128 + ko + ((lane >> 3) & 1) * 16);
            uint32_t bfh[2], bfl[2];
            ldsm_x2(bfh, bh + boff);
            ldsm_x2(bfl, bl + boff);
#pragma unroll
            for (int i = 0; i < 4; i++) {
                mma16816(acc[i][j], afh[i], bfh);
                mma16816(acc[i][j], afh[i], bfl);
                mma16816(acc[i][j], afl[i], bfh);
            }
        }
    }

    // --------------- epilogue v2.1: smem-transposed, coalesced ---------------
    const int g = lane >> 2, tig = lane & 3;
    const int cloc = tid & 127;        // channel within chunk
    const int q = tid >> 7;            // edge quarter 0..3
    const unsigned lmask = s_mask[q];

#pragma unroll
    for (int ch = 0; ch < 2; ch++) {
        __syncthreads();               // previous phase reads done / MMA done
        if ((wn >> 2) == ch) {         // 8 warps stage their 128 channels
            int wnl = wn & 3;
#pragma unroll
            for (int i = 0; i < 4; i++)
#pragma unroll
                for (int half = 0; half < 2; half++) {
                    int row = wm * 64 + i * 16 + half * 8 + g;
#pragma unroll
                    for (int j = 0; j < 4; j++) {
                        float2 v = half ? make_float2(acc[i][j][2], acc[i][j][3])
                                        : make_float2(acc[i][j][0], acc[i][j][1]);
                        *(float2*)(stage + row * SROW + wnl * 32 + j * 8 + 2 * tig) = v;
                    }
                }
        }
        __syncthreads();
        // dst-major reduce: 512 threads = 128 ch x 4 quarters
        int cg = ch * 128 + cloc;
        float a = 0.f;
#pragma unroll
        for (int i = 0; i < 32; i++) {
            int e = q * 32 + i;
            int4 cs = s_csr[e];
            float ev = stage[e * SROW + cloc];
            a = fmaf(ev, __ldg(&x[(size_t)cs.y * CH + cg]), a);
            if ((lmask >> i) & 1u) {
                if (cs.z >= 0)
                    asm volatile("red.global.add.f32 [%0], %1;"
                                 :: "l"(g_agg + (size_t)cs.z * CH + cg), "f"(a) : "memory");
                a = 0.f;
            }
        }
    }
}

// ---------------------------------------------------------------------------
// K5: agg fp32 -> bf16 hi/lo; self-clean g_agg and g_sum/g_sumsq
// ---------------------------------------------------------------------------
__global__ void __launch_bounds__(256) agg_split() {
    int gid = blockIdx.x * blockDim.x + threadIdx.x;
    int stride = gridDim.x * blockDim.x;
    const int total = NNODES * CH / 4;
    float4* a4 = (float4*)g_agg;
    for (int i = gid; i < total; i += stride) {
        float4 v = a4[i];
        ull hb, lb; split4(v, hb, lb);
        ((ull*)g_agg_hi)[i] = hb;
        ((ull*)g_agg_lo)[i] = lb;
        a4[i] = make_float4(0.f, 0.f, 0.f, 0.f);
    }
    if (gid < CH) { g_sum[gid] = 0.f; g_sumsq[gid] = 0.f; }
}

// ---------------------------------------------------------------------------
// K6: node MMA. grid (157, 4), 256 thr, tile 128x128, dbl buffer.
// ---------------------------------------------------------------------------
__global__ void __launch_bounds__(256) node_mma(
    const float* __restrict__ b_rel, float* __restrict__ out)
{
    extern __shared__ char dsm[];
    char* base = (char*)(((uintptr_t)dsm + 1023) & ~(uintptr_t)1023);

    const int tid = threadIdx.x;
    const int lane = tid & 31;
    const int wid = tid >> 5;
    const int wm = wid >> 2;
    const int wn = wid & 3;
    const int m0 = blockIdx.x * 128;
    const int yb = blockIdx.y;
    const bool isH = (yb < 2);
    const int n0 = (isH ? yb : yb - 2) * 128;

    const __nv_bfloat16* Asrc_hi[2];
    const __nv_bfloat16* Asrc_lo[2];
    const __nv_bfloat16* Bsrc_hi[2];
    const __nv_bfloat16* Bsrc_lo[2];
    int nsrc;
    if (isH) {
        nsrc = 2;
        Asrc_hi[0] = g_agg_hi; Asrc_lo[0] = g_agg_lo;
        Bsrc_hi[0] = g_WTrel_hi; Bsrc_lo[0] = g_WTrel_lo;
        Asrc_hi[1] = g_x_hi; Asrc_lo[1] = g_x_lo;
        Bsrc_hi[1] = g_WTroot_hi; Bsrc_lo[1] = g_WTroot_lo;
    } else {
        nsrc = 1;
        Asrc_hi[0] = g_x_hi; Asrc_lo[0] = g_x_lo;
        Bsrc_hi[0] = g_WTres_hi; Bsrc_lo[0] = g_WTres_lo;
    }
    const int np = nsrc * 4;

    auto prefetch = [&](int p, int b) {
        int s = p >> 2, kc = p & 3;
        int k0b = kc * 128;
        char* Ah = base + b * 65536;
        char* Al = Ah + 16384;
        char* Bh = Ah + 32768;
        char* Bl = Ah + 49152;
        const char* ahp = (const char*)Asrc_hi[s];
        const char* alp = (const char*)Asrc_lo[s];
        const char* bhp = (const char*)Bsrc_hi[s];
        const char* blp = (const char*)Bsrc_lo[s];
        for (int idx = tid; idx < 1024; idx += 256) {
            int row = idx >> 3, q = idx & 7;
            int r = m0 + row;
            int ok = (r < NNODES);
            int rr = ok ? r : 0;
            uint32_t off = SWZ(row * 128 + q * 16);
            cpa16(smem_u32(Ah) + off, ahp + (size_t)rr * 512 + k0b + q * 16, ok);
            cpa16(smem_u32(Al) + off, alp + (size_t)rr * 512 + k0b + q * 16, ok);
        }
        for (int idx = tid; idx < 1024; idx += 256) {
            int n = idx >> 3, q = idx & 7;
            uint32_t off = SWZ(n * 128 + q * 16);
            cpa16(smem_u32(Bh) + off, bhp + (size_t)(n0 + n) * 512 + k0b + q * 16, 1);
            cpa16(smem_u32(Bl) + off, blp + (size_t)(n0 + n) * 512 + k0b + q * 16, 1);
        }
        CP_COMMIT();
    };

    float acc[4][4][4];
#pragma unroll
    for (int i = 0; i < 4; i++)
#pragma unroll
        for (int j = 0; j < 4; j++)
#pragma unroll
            for (int k = 0; k < 4; k++) acc[i][j][k] = 0.f;

    prefetch(0, 0);
    for (int p = 0; p < np; p++) {
        if (p + 1 < np) {
            prefetch(p + 1, (p + 1) & 1);
            CP_WAIT(1);
        } else {
            CP_WAIT(0);
        }
        __syncthreads();
        char* Ab = base + (p & 1) * 65536;
        const uint32_t ah = smem_u32(Ab), al = ah + 16384;
        const uint32_t bh = ah + 32768, bl = ah + 49152;
#pragma unroll
        for (int ks = 0; ks < 4; ks++) {
            int ko = ks * 32;
            uint32_t afh[4][4], afl[4][4];
#pragma unroll
            for (int i = 0; i < 4; i++) {
                uint32_t aoff = SWZ((wm * 64 + i * 16 + (lane & 15)) * 128 + ko + (lane >> 4) * 16);
                ldsm_x4(afh[i], ah + aoff);
                ldsm_x4(afl[i], al + aoff);
            }
#pragma unroll
            for (int j = 0; j < 4; j++) {
                uint32_t boff = SWZ((wn * 32 + j * 8 + (lane & 7)) * 128 + ko + ((lane >> 3) & 1) * 16);
                uint32_t bfh[2], bfl[2];
                ldsm_x2(bfh, bh + boff);
                ldsm_x2(bfl, bl + boff);
#pragma unroll
                for (int i = 0; i < 4; i++) {
                    mma16816(acc[i][j], afh[i], bfh);
                    mma16816(acc[i][j], afh[i], bfl);
                    mma16816(acc[i][j], afl[i], bfh);
                }
            }
        }
        __syncthreads();
    }

    const int g = lane >> 2, tig = lane & 3;
    if (isH) {
        float cs[4][2], cq[4][2];
#pragma unroll
        for (int j = 0; j < 4; j++) { cs[j][0] = cs[j][1] = cq[j][0] = cq[j][1] = 0.f; }
#pragma unroll
        for (int j = 0; j < 4; j++) {
            int c = n0 + wn * 32 + j * 8 + 2 * tig;
            float2 b = *(const float2*)(b_rel + c);
#pragma unroll
            for (int i = 0; i < 4; i++) {
                int r0 = m0 + wm * 64 + i * 16 + g;
                if (r0 < NNODES) {
                    float v0 = fmaxf(acc[i][j][0] + b.x, 0.f);
                    float v1 = fmaxf(acc[i][j][1] + b.y, 0.f);
                    *(float2*)(g_h + (size_t)r0 * CH + c) = make_float2(v0, v1);
                    cs[j][0] += v0; cs[j][1] += v1;
                    cq[j][0] += v0 * v0; cq[j][1] += v1 * v1;
                }
                if (r0 + 8 < NNODES) {
                    float v0 = fmaxf(acc[i][j][2] + b.x, 0.f);
                    float v1 = fmaxf(acc[i][j][3] + b.y, 0.f);
                    *(float2*)(g_h + (size_t)(r0 + 8) * CH + c) = make_float2(v0, v1);
                    cs[j][0] += v0; cs[j][1] += v1;
                    cq[j][0] += v0 * v0; cq[j][1] += v1 * v1;
                }
            }
        }
#pragma unroll
        for (int j = 0; j < 4; j++)
#pragma unroll
            for (int t2 = 0; t2 < 2; t2++) {
#pragma unroll
                for (int m = 4; m <= 16; m <<= 1) {
                    cs[j][t2] += __shfl_xor_sync(0xFFFFFFFF, cs[j][t2], m);
                    cq[j][t2] += __shfl_xor_sync(0xFFFFFFFF, cq[j][t2], m);
                }
            }
        if (lane < 4) {
#pragma unroll
            for (int j = 0; j < 4; j++) {
                int c = n0 + wn * 32 + j * 8 + 2 * lane;
                atomicAdd(&g_sum[c], cs[j][0]);
                atomicAdd(&g_sum[c + 1], cs[j][1]);
                atomicAdd(&g_sumsq[c], cq[j][0]);
                atomicAdd(&g_sumsq[c + 1], cq[j][1]);
            }
        }
    } else {
#pragma unroll
        for (int j = 0; j < 4; j++) {
            int c = n0 + wn * 32 + j * 8 + 2 * tig;
#pragma unroll
            for (int i = 0; i < 4; i++) {
                int r0 = m0 + wm * 64 + i * 16 + g;
                if (r0 < NNODES)
                    *(float2*)(out + (size_t)r0 * CH + c) = make_float2(acc[i][j][0], acc[i][j][1]);
                if (r0 + 8 < NNODES)
                    *(float2*)(out + (size_t)(r0 + 8) * CH + c) = make_float2(acc[i][j][2], acc[i][j][3]);
            }
        }
    }
}

// ---------------------------------------------------------------------------
// K7: finalize
// ---------------------------------------------------------------------------
__global__ void __launch_bounds__(256) finalize(
    const float* __restrict__ gamma, const float* __restrict__ beta,
    float* __restrict__ out)
{
    __shared__ float ssc[CH], ssh[CH];
    int t = threadIdx.x;
    {
        float m = g_sum[t] * (1.0f / NNODES);
        float var = g_sumsq[t] * (1.0f / NNODES) - m * m;
        float is = rsqrtf(var + 1e-5f);
        float sc = is * __ldg(&gamma[t]);
        ssc[t] = sc;
        ssh[t] = __ldg(&beta[t]) - m * sc;
    }
    __syncthreads();
    int idx = blockIdx.x * blockDim.x + t;
    int stride = gridDim.x * blockDim.x;
    const int total = NNODES * CH / 4;
    const float4* h4 = (const float4*)g_h;
    float4* o4 = (float4*)out;
    for (int i = idx; i < total; i += stride) {
        int c = (i & 63) * 4;
        float4 h = h4[i];
        float4 o = o4[i];
        float4 sc = *(const float4*)&ssc[c];
        float4 sh = *(const float4*)&ssh[c];
        o4[i] = make_float4(fmaf(h.x, sc.x, sh.x) + o.x,
                            fmaf(h.y, sc.y, sh.y) + o.y,
                            fmaf(h.z, sc.z, sh.z) + o.z,
                            fmaf(h.w, sc.w, sh.w) + o.w);
    }
}

// ---------------------------------------------------------------------------
extern "C" void kernel_launch(void* const* d_in, const int* in_sizes, int n_in,
                              void* d_out, int out_size) {
    const float* x      = (const float*)d_in[0];
    const int*   ei     = (const int*)d_in[1];
    const float* ea     = (const float*)d_in[2];
    const float* W_edge = (const float*)d_in[3];
    const float* W_rel  = (const float*)d_in[4];
    const float* b_rel  = (const float*)d_in[5];
    const float* W_root = (const float*)d_in[6];
    const float* gamma  = (const float*)d_in[7];
    const float* beta   = (const float*)d_in[8];
    const float* W_res  = (const float*)d_in[9];
    int E = in_sizes[1] / 2;
    float* out = (float*)d_out;

    const int EGEMM_SMEM = 98304 + 2048 + 64 + 1024;
    const int NODE_SMEM = 131072 + 1024;
    cudaFuncSetAttribute(egemm_fused, cudaFuncAttributeMaxDynamicSharedMemorySize, EGEMM_SMEM);
    cudaFuncSetAttribute(node_mma, cudaFuncAttributeMaxDynamicSharedMemorySize, NODE_SMEM);

    int nh = (E + 255) / 256;
    hist_prep<<<nh + 256 + 1184, 256>>>(ei, W_edge, W_rel, W_root, W_res, x, E, nh);  // 1
    scan_kernel<<<1, 1024>>>(E);                                                      // 2
    fill_kernel<<<nh, 256>>>(ei, E);                                                  // 3
    egemm_fused<<<(E + 127) / 128, 512, EGEMM_SMEM>>>(ea, x, E);                      // 4 (profiled)
    agg_split<<<1280, 256>>>();                                                       // 5
    dim3 gn((NNODES + 127) / 128, 4);
    node_mma<<<gn, 256, NODE_SMEM>>>(b_rel, out);                                     // 6
    finalize<<<592, 256>>>(gamma, beta, out);                                         // 7
}

// round 11
// speedup vs baseline: 1.0932x; 1.0932x over previous
#include <cuda_runtime.h>
#include <cuda_bf16.h>
#include <cstdint>

#define NNODES 20000
#define CH 256
#define ECH 64
#define MAXE 320000

typedef unsigned long long ull;

// ---------------- scratch (__device__ globals; no allocation) ----------------
__device__ float g_agg[NNODES * CH];          // fp32 aggregation target (self-cleaned)
__device__ float g_h[NNODES * CH];
__device__ int   g_cnt[NNODES];               // self-cleaned by scan
__device__ int   g_rowstart[NNODES + 1];
__device__ int   g_cursor[NNODES];
__device__ int4  g_csr4[MAXE];                // {eid, src, dst, 0}, dst-sorted
__device__ float g_sum[CH];                   // self-cleaned by agg_split
__device__ float g_sumsq[CH];
__device__ __align__(16) __nv_bfloat16 g_x_hi[NNODES * CH], g_x_lo[NNODES * CH];
__device__ __align__(16) __nv_bfloat16 g_agg_hi[NNODES * CH], g_agg_lo[NNODES * CH];
__device__ __align__(16) __nv_bfloat16 g_WTe_hi[CH * ECH], g_WTe_lo[CH * ECH];
__device__ __align__(16) __nv_bfloat16 g_WTrel_hi[CH * CH], g_WTrel_lo[CH * CH];
__device__ __align__(16) __nv_bfloat16 g_WTroot_hi[CH * CH], g_WTroot_lo[CH * CH];
__device__ __align__(16) __nv_bfloat16 g_WTres_hi[CH * CH], g_WTres_lo[CH * CH];

// ---------------- helpers ----------------
__device__ __forceinline__ uint32_t smem_u32(const void* p) {
    uint32_t a;
    asm("{ .reg .u64 t; cvta.to.shared.u64 t, %1; cvt.u32.u64 %0, t; }" : "=r"(a) : "l"(p));
    return a;
}
#define SWZ(off) ((off) ^ (((off) >> 3) & 0x70))

__device__ __forceinline__ void cpa16(uint32_t dst, const void* src, int pred16) {
    asm volatile("cp.async.cg.shared.global [%0], [%1], 16, %2;"
                 :: "r"(dst), "l"(src), "r"(pred16 ? 16 : 0) : "memory");
}
#define CP_COMMIT() asm volatile("cp.async.commit_group;" ::: "memory")
#define CP_WAIT(n)  asm volatile("cp.async.wait_group %0;" :: "n"(n) : "memory")

__device__ __forceinline__ void ldsm_x4(uint32_t* r, uint32_t addr) {
    asm volatile("ldmatrix.sync.aligned.m8n8.x4.shared.b16 {%0,%1,%2,%3}, [%4];"
        : "=r"(r[0]), "=r"(r[1]), "=r"(r[2]), "=r"(r[3]) : "r"(addr));
}
__device__ __forceinline__ void ldsm_x2(uint32_t* r, uint32_t addr) {
    asm volatile("ldmatrix.sync.aligned.m8n8.x2.shared.b16 {%0,%1}, [%2];"
        : "=r"(r[0]), "=r"(r[1]) : "r"(addr));
}
__device__ __forceinline__ void mma16816(float* c, const uint32_t* a, const uint32_t* b) {
    asm volatile("mma.sync.aligned.m16n8k16.row.col.f32.bf16.bf16.f32 "
        "{%0,%1,%2,%3}, {%4,%5,%6,%7}, {%8,%9}, {%0,%1,%2,%3};"
        : "+f"(c[0]), "+f"(c[1]), "+f"(c[2]), "+f"(c[3])
        : "r"(a[0]), "r"(a[1]), "r"(a[2]), "r"(a[3]), "r"(b[0]), "r"(b[1]));
}
__device__ __forceinline__ void split4(float4 v, ull& hb, ull& lb) {
    __nv_bfloat16 h0 = __float2bfloat16(v.x), h1 = __float2bfloat16(v.y);
    __nv_bfloat16 h2 = __float2bfloat16(v.z), h3 = __float2bfloat16(v.w);
    __nv_bfloat16 l0 = __float2bfloat16(v.x - __bfloat162float(h0));
    __nv_bfloat16 l1 = __float2bfloat16(v.y - __bfloat162float(h1));
    __nv_bfloat16 l2 = __float2bfloat16(v.z - __bfloat162float(h2));
    __nv_bfloat16 l3 = __float2bfloat16(v.w - __bfloat162float(h3));
    hb = (ull)__bfloat16_as_ushort(h0) | ((ull)__bfloat16_as_ushort(h1) << 16) |
         ((ull)__bfloat16_as_ushort(h2) << 32) | ((ull)__bfloat16_as_ushort(h3) << 48);
    lb = (ull)__bfloat16_as_ushort(l0) | ((ull)__bfloat16_as_ushort(l1) << 16) |
         ((ull)__bfloat16_as_ushort(l2) << 32) | ((ull)__bfloat16_as_ushort(l3) << 48);
}

// ---------------------------------------------------------------------------
// K1: hist + weight prep + x split (disjoint block ranges)
// ---------------------------------------------------------------------------
__global__ void __launch_bounds__(256) hist_prep(
    const int* __restrict__ ei,
    const float* __restrict__ We, const float* __restrict__ Wrel,
    const float* __restrict__ Wroot, const float* __restrict__ Wres,
    const float* __restrict__ x, int E, int nh)
{
    int b = blockIdx.x;
    int t = threadIdx.x;
    if (b < nh) {
        int e = b * 256 + t;
        if (e < E) atomicAdd(&g_cnt[__ldg(&ei[E + e])], 1);
    } else if (b < nh + 256) {
        int n = b - nh, k = t;
        if (k < ECH) {
            float v = __ldg(&We[(size_t)k * CH + n]);
            __nv_bfloat16 h = __float2bfloat16(v);
            g_WTe_hi[n * ECH + k] = h;
            g_WTe_lo[n * ECH + k] = __float2bfloat16(v - __bfloat162float(h));
        }
        {
            float v = __ldg(&Wrel[(size_t)k * CH + n]);
            __nv_bfloat16 h = __float2bfloat16(v);
            g_WTrel_hi[n * CH + k] = h;
            g_WTrel_lo[n * CH + k] = __float2bfloat16(v - __bfloat162float(h));
        }
        {
            float v = __ldg(&Wroot[(size_t)k * CH + n]);
            __nv_bfloat16 h = __float2bfloat16(v);
            g_WTroot_hi[n * CH + k] = h;
            g_WTroot_lo[n * CH + k] = __float2bfloat16(v - __bfloat162float(h));
        }
        {
            float v = __ldg(&Wres[(size_t)k * CH + n]);
            __nv_bfloat16 h = __float2bfloat16(v);
            g_WTres_hi[n * CH + k] = h;
            g_WTres_lo[n * CH + k] = __float2bfloat16(v - __bfloat162float(h));
        }
    } else {
        const int total = NNODES * CH / 4;
        int idx = (b - nh - 256) * 256 + t;
        int stride = (gridDim.x - nh - 256) * 256;
        for (int i = idx; i < total; i += stride) {
            float4 v = __ldg(((const float4*)x) + i);
            ull hb, lb; split4(v, hb, lb);
            ((ull*)g_x_hi)[i] = hb;
            ((ull*)g_x_lo)[i] = lb;
        }
    }
}

// ---------------------------------------------------------------------------
// K2: scan (reads g_cnt, zeroes it for the next replay)
// ---------------------------------------------------------------------------
__global__ void __launch_bounds__(1024) scan_kernel(int E) {
    __shared__ int sp[1024];
    const int t = threadIdx.x;
    const int CHUNK = (NNODES + 1023) / 1024;
    int beg = t * CHUNK;
    int end = min(beg + CHUNK, NNODES);
    int mysum = 0;
    for (int i = beg; i < end; i++) mysum += g_cnt[i];
    sp[t] = mysum;
    __syncthreads();
#pragma unroll
    for (int off = 1; off < 1024; off <<= 1) {
        int v = (t >= off) ? sp[t - off] : 0;
        __syncthreads();
        sp[t] += v;
        __syncthreads();
    }
    int running = sp[t] - mysum;
    for (int i = beg; i < end; i++) {
        int c = g_cnt[i];
        g_cnt[i] = 0;               // self-clean for next replay
        g_rowstart[i] = running;
        g_cursor[i] = running;
        running += c;
    }
    if (t == 1023) g_rowstart[NNODES] = E;
}

// ---------------------------------------------------------------------------
// K3: fill CSR as int4 {eid, src, dst, 0}
// ---------------------------------------------------------------------------
__global__ void fill_kernel(const int* __restrict__ ei, int E) {
    int e = blockIdx.x * blockDim.x + threadIdx.x;
    if (e < E) {
        int dst = __ldg(&ei[E + e]);
        int src = __ldg(&ei[e]);
        int pos = atomicAdd(&g_cursor[dst], 1);
        g_csr4[pos] = make_int4(e, src, dst, 0);
    }
}

// ---------------------------------------------------------------------------
// K4 (profiled): fused edge GEMM + message + aggregation (R8-proven version).
// Rows = CSR-sorted edges. Tile 128m x 256n, K=64 single chunk, 512 thr.
// Epilogue: v = e * x[src][c], shfl segmented-reduce over 8 consecutive rows
// (sorted by dst), heads do red.global.add.v2.f32 into g_agg[dst].
// smem: Ah 16K | Al 16K | Bh 32K | Bl 32K | csr 2K
// ---------------------------------------------------------------------------
__global__ void __launch_bounds__(512, 2) egemm_fused(
    const float* __restrict__ ea, const float* __restrict__ x, int E)
{
    extern __shared__ char dsm[];
    char* base = (char*)(((uintptr_t)dsm + 1023) & ~(uintptr_t)1023);
    char* Ah = base;
    char* Al = base + 16384;
    char* Bh = base + 32768;
    char* Bl = base + 65536;
    int4* s_csr = (int4*)(base + 98304);

    const int tid = threadIdx.x;
    const int lane = tid & 31;
    const int wid = tid >> 5;
    const int wm = wid >> 3;     // 0..1
    const int wn = wid & 7;      // 0..7
    const int m0 = blockIdx.x * 128;

    // stage CSR tile
    if (tid < 128) {
        int r = m0 + tid;
        s_csr[tid] = (r < E) ? __ldg(&g_csr4[r]) : make_int4(0, 0, -1, 0);
    }
    __syncthreads();

    // A: gather ea rows in CSR order, split fp32 -> hi/lo bf16
    for (int idx = tid; idx < 2048; idx += 512) {
        int row = idx >> 4, q = idx & 15;
        int4 cs = s_csr[row];
        float4 v = make_float4(0.f, 0.f, 0.f, 0.f);
        if (cs.z >= 0) v = __ldg((const float4*)(ea + (size_t)cs.x * ECH) + q);
        ull hb, lb; split4(v, hb, lb);
        uint32_t off = SWZ(row * 128 + q * 8);
        *(ull*)(Ah + off) = hb;
        *(ull*)(Al + off) = lb;
    }
    // B: WTe 256 x 64 bf16 hi/lo
    {
        const uint4* sh = (const uint4*)g_WTe_hi;
        const uint4* sl = (const uint4*)g_WTe_lo;
        for (int idx = tid; idx < 2048; idx += 512) {
            int n = idx >> 3, q = idx & 7;
            uint32_t off = SWZ(n * 128 + q * 16);
            *(uint4*)(Bh + off) = __ldg(&sh[idx]);
            *(uint4*)(Bl + off) = __ldg(&sl[idx]);
        }
    }
    __syncthreads();

    float acc[4][4][4];
#pragma unroll
    for (int i = 0; i < 4; i++)
#pragma unroll
        for (int j = 0; j < 4; j++)
#pragma unroll
            for (int k = 0; k < 4; k++) acc[i][j][k] = 0.f;

    const uint32_t ah = smem_u32(Ah), al = smem_u32(Al);
    const uint32_t bh = smem_u32(Bh), bl = smem_u32(Bl);

#pragma unroll
    for (int ks = 0; ks < 4; ks++) {
        int ko = ks * 32;
        uint32_t afh[4][4], afl[4][4];
#pragma unroll
        for (int i = 0; i < 4; i++) {
            uint32_t aoff = SWZ((wm * 64 + i * 16 + (lane & 15)) * 128 + ko + (lane >> 4) * 16);
            ldsm_x4(afh[i], ah + aoff);
            ldsm_x4(afl[i], al + aoff);
        }
#pragma unroll
        for (int j = 0; j < 4; j++) {
            uint32_t boff = SWZ((wn * 32 + j * 8 + (lane & 7)) * 128 + ko + ((lane >> 3) & 1) * 16);
            uint32_t bfh[2], bfl[2];
            ldsm_x2(bfh, bh + boff);
            ldsm_x2(bfl, bl + boff);
#pragma unroll
            for (int i = 0; i < 4; i++) {
                mma16816(acc[i][j], afh[i], bfh);
                mma16816(acc[i][j], afh[i], bfl);
                mma16816(acc[i][j], afl[i], bfh);
            }
        }
    }

    // fused epilogue (R8): multiply by x[src], shfl segment-reduce, RED
#pragma unroll
    for (int i = 0; i < 4; i++) {
#pragma unroll
        for (int half = 0; half < 2; half++) {
            const int g = lane >> 2, tig = lane & 3;
            int rr = wm * 64 + i * 16 + half * 8 + g;
            int4 cs = s_csr[rr];
            int d = cs.z;
            int dprev = __shfl_up_sync(0xFFFFFFFFu, d, 4);
            bool head = (g == 0) || (dprev != d);
            int dn4 = __shfl_down_sync(0xFFFFFFFFu, d, 4);
            int dn8 = __shfl_down_sync(0xFFFFFFFFu, d, 8);
            int dn16 = __shfl_down_sync(0xFFFFFFFFu, d, 16);
            bool m4 = (g < 7) && (dn4 == d);
            bool m8 = (g < 6) && (dn8 == d);
            bool m16 = (g < 4) && (dn16 == d);
            const float* xr = x + (size_t)cs.y * CH;
            float* arow = g_agg + (size_t)(d < 0 ? 0 : d) * CH;
#pragma unroll
            for (int j = 0; j < 4; j++) {
                int c = wn * 32 + j * 8 + 2 * tig;
                float2 xv = __ldg((const float2*)(xr + c));
                float vx = (half ? acc[i][j][2] : acc[i][j][0]) * xv.x;
                float vy = (half ? acc[i][j][3] : acc[i][j][1]) * xv.y;
                float t;
                t = __shfl_down_sync(0xFFFFFFFFu, vx, 4);  vx += m4 ? t : 0.f;
                t = __shfl_down_sync(0xFFFFFFFFu, vy, 4);  vy += m4 ? t : 0.f;
                t = __shfl_down_sync(0xFFFFFFFFu, vx, 8);  vx += m8 ? t : 0.f;
                t = __shfl_down_sync(0xFFFFFFFFu, vy, 8);  vy += m8 ? t : 0.f;
                t = __shfl_down_sync(0xFFFFFFFFu, vx, 16); vx += m16 ? t : 0.f;
                t = __shfl_down_sync(0xFFFFFFFFu, vy, 16); vy += m16 ? t : 0.f;
                if (head && d >= 0) {
                    asm volatile("red.global.add.v2.f32 [%0], {%1, %2};"
                                 :: "l"(arow + c), "f"(vx), "f"(vy) : "memory");
                }
            }
        }
    }
}

// ---------------------------------------------------------------------------
// K5: agg fp32 -> bf16 hi/lo; self-clean g_agg and g_sum/g_sumsq
// ---------------------------------------------------------------------------
__global__ void __launch_bounds__(256) agg_split() {
    int gid = blockIdx.x * blockDim.x + threadIdx.x;
    int stride = gridDim.x * blockDim.x;
    const int total = NNODES * CH / 4;
    float4* a4 = (float4*)g_agg;
    for (int i = gid; i < total; i += stride) {
        float4 v = a4[i];
        ull hb, lb; split4(v, hb, lb);
        ((ull*)g_agg_hi)[i] = hb;
        ((ull*)g_agg_lo)[i] = lb;
        a4[i] = make_float4(0.f, 0.f, 0.f, 0.f);
    }
    if (gid < CH) { g_sum[gid] = 0.f; g_sumsq[gid] = 0.f; }
}

// ---------------------------------------------------------------------------
// K6: node MMA. grid (157, 4), 256 thr, tile 128x128.
// SINGLE 64KB buffer -> 3 CTAs/SM; cross-CTA overlap replaces double-buffer.
// ---------------------------------------------------------------------------
__global__ void __launch_bounds__(256, 3) node_mma(
    const float* __restrict__ b_rel, float* __restrict__ out)
{
    extern __shared__ char dsm[];
    char* base = (char*)(((uintptr_t)dsm + 1023) & ~(uintptr_t)1023);
    char* Ah = base;
    char* Al = base + 16384;
    char* Bh = base + 32768;
    char* Bl = base + 49152;

    const int tid = threadIdx.x;
    const int lane = tid & 31;
    const int wid = tid >> 5;
    const int wm = wid >> 2;
    const int wn = wid & 3;
    const int m0 = blockIdx.x * 128;
    const int yb = blockIdx.y;
    const bool isH = (yb < 2);
    const int n0 = (isH ? yb : yb - 2) * 128;

    const __nv_bfloat16* Asrc_hi[2];
    const __nv_bfloat16* Asrc_lo[2];
    const __nv_bfloat16* Bsrc_hi[2];
    const __nv_bfloat16* Bsrc_lo[2];
    int nsrc;
    if (isH) {
        nsrc = 2;
        Asrc_hi[0] = g_agg_hi; Asrc_lo[0] = g_agg_lo;
        Bsrc_hi[0] = g_WTrel_hi; Bsrc_lo[0] = g_WTrel_lo;
        Asrc_hi[1] = g_x_hi; Asrc_lo[1] = g_x_lo;
        Bsrc_hi[1] = g_WTroot_hi; Bsrc_lo[1] = g_WTroot_lo;
    } else {
        nsrc = 1;
        Asrc_hi[0] = g_x_hi; Asrc_lo[0] = g_x_lo;
        Bsrc_hi[0] = g_WTres_hi; Bsrc_lo[0] = g_WTres_lo;
    }
    const int np = nsrc * 4;

    auto prefetch = [&](int p) {
        int s = p >> 2, kc = p & 3;
        int k0b = kc * 128;
        const char* ahp = (const char*)Asrc_hi[s];
        const char* alp = (const char*)Asrc_lo[s];
        const char* bhp = (const char*)Bsrc_hi[s];
        const char* blp = (const char*)Bsrc_lo[s];
        for (int idx = tid; idx < 1024; idx += 256) {
            int row = idx >> 3, q = idx & 7;
            int r = m0 + row;
            int ok = (r < NNODES);
            int rr = ok ? r : 0;
            uint32_t off = SWZ(row * 128 + q * 16);
            cpa16(smem_u32(Ah) + off, ahp + (size_t)rr * 512 + k0b + q * 16, ok);
            cpa16(smem_u32(Al) + off, alp + (size_t)rr * 512 + k0b + q * 16, ok);
        }
        for (int idx = tid; idx < 1024; idx += 256) {
            int n = idx >> 3, q = idx & 7;
            uint32_t off = SWZ(n * 128 + q * 16);
            cpa16(smem_u32(Bh) + off, bhp + (size_t)(n0 + n) * 512 + k0b + q * 16, 1);
            cpa16(smem_u32(Bl) + off, blp + (size_t)(n0 + n) * 512 + k0b + q * 16, 1);
        }
        CP_COMMIT();
    };

    float acc[4][4][4];
#pragma unroll
    for (int i = 0; i < 4; i++)
#pragma unroll
        for (int j = 0; j < 4; j++)
#pragma unroll
            for (int k = 0; k < 4; k++) acc[i][j][k] = 0.f;

    const uint32_t ah = smem_u32(Ah), al = smem_u32(Al);
    const uint32_t bh = smem_u32(Bh), bl = smem_u32(Bl);

    for (int p = 0; p < np; p++) {
        prefetch(p);
        CP_WAIT(0);
        __syncthreads();
#pragma unroll
        for (int ks = 0; ks < 4; ks++) {
            int ko = ks * 32;
            uint32_t afh[4][4], afl[4][4];
#pragma unroll
            for (int i = 0; i < 4; i++) {
                uint32_t aoff = SWZ((wm * 64 + i * 16 + (lane & 15)) * 128 + ko + (lane >> 4) * 16);
                ldsm_x4(afh[i], ah + aoff);
                ldsm_x4(afl[i], al + aoff);
            }
#pragma unroll
            for (int j = 0; j < 4; j++) {
                uint32_t boff = SWZ((wn * 32 + j * 8 + (lane & 7)) * 128 + ko + ((lane >> 3) & 1) * 16);
                uint32_t bfh[2], bfl[2];
                ldsm_x2(bfh, bh + boff);
                ldsm_x2(bfl, bl + boff);
#pragma unroll
                for (int i = 0; i < 4; i++) {
                    mma16816(acc[i][j], afh[i], bfh);
                    mma16816(acc[i][j], afh[i], bfl);
                    mma16816(acc[i][j], afl[i], bfh);
                }
            }
        }
        __syncthreads();
    }

    const int g = lane >> 2, tig = lane & 3;
    if (isH) {
        float cs[4][2], cq[4][2];
#pragma unroll
        for (int j = 0; j < 4; j++) { cs[j][0] = cs[j][1] = cq[j][0] = cq[j][1] = 0.f; }
#pragma unroll
        for (int j = 0; j < 4; j++) {
            int c = n0 + wn * 32 + j * 8 + 2 * tig;
            float2 b = *(const float2*)(b_rel + c);
#pragma unroll
            for (int i = 0; i < 4; i++) {
                int r0 = m0 + wm * 64 + i * 16 + g;
                if (r0 < NNODES) {
                    float v0 = fmaxf(acc[i][j][0] + b.x, 0.f);
                    float v1 = fmaxf(acc[i][j][1] + b.y, 0.f);
                    *(float2*)(g_h + (size_t)r0 * CH + c) = make_float2(v0, v1);
                    cs[j][0] += v0; cs[j][1] += v1;
                    cq[j][0] += v0 * v0; cq[j][1] += v1 * v1;
                }
                if (r0 + 8 < NNODES) {
                    float v0 = fmaxf(acc[i][j][2] + b.x, 0.f);
                    float v1 = fmaxf(acc[i][j][3] + b.y, 0.f);
                    *(float2*)(g_h + (size_t)(r0 + 8) * CH + c) = make_float2(v0, v1);
                    cs[j][0] += v0; cs[j][1] += v1;
                    cq[j][0] += v0 * v0; cq[j][1] += v1 * v1;
                }
            }
        }
#pragma unroll
        for (int j = 0; j < 4; j++)
#pragma unroll
            for (int t2 = 0; t2 < 2; t2++) {
#pragma unroll
                for (int m = 4; m <= 16; m <<= 1) {
                    cs[j][t2] += __shfl_xor_sync(0xFFFFFFFF, cs[j][t2], m);
                    cq[j][t2] += __shfl_xor_sync(0xFFFFFFFF, cq[j][t2], m);
                }
            }
        if (lane < 4) {
#pragma unroll
            for (int j = 0; j < 4; j++) {
                int c = n0 + wn * 32 + j * 8 + 2 * lane;
                atomicAdd(&g_sum[c], cs[j][0]);
                atomicAdd(&g_sum[c + 1], cs[j][1]);
                atomicAdd(&g_sumsq[c], cq[j][0]);
                atomicAdd(&g_sumsq[c + 1], cq[j][1]);
            }
        }
    } else {
#pragma unroll
        for (int j = 0; j < 4; j++) {
            int c = n0 + wn * 32 + j * 8 + 2 * tig;
#pragma unroll
            for (int i = 0; i < 4; i++) {
                int r0 = m0 + wm * 64 + i * 16 + g;
                if (r0 < NNODES)
                    *(float2*)(out + (size_t)r0 * CH + c) = make_float2(acc[i][j][0], acc[i][j][1]);
                if (r0 + 8 < NNODES)
                    *(float2*)(out + (size_t)(r0 + 8) * CH + c) = make_float2(acc[i][j][2], acc[i][j][3]);
            }
        }
    }
}

// ---------------------------------------------------------------------------
// K7: finalize
// ---------------------------------------------------------------------------
__global__ void __launch_bounds__(256) finalize(
    const float* __restrict__ gamma, const float* __restrict__ beta,
    float* __restrict__ out)
{
    __shared__ float ssc[CH], ssh[CH];
    int t = threadIdx.x;
    {
        float m = g_sum[t] * (1.0f / NNODES);
        float var = g_sumsq[t] * (1.0f / NNODES) - m * m;
        float is = rsqrtf(var + 1e-5f);
        float sc = is * __ldg(&gamma[t]);
        ssc[t] = sc;
        ssh[t] = __ldg(&beta[t]) - m * sc;
    }
    __syncthreads();
    int idx = blockIdx.x * blockDim.x + t;
    int stride = gridDim.x * blockDim.x;
    const int total = NNODES * CH / 4;
    const float4* h4 = (const float4*)g_h;
    float4* o4 = (float4*)out;
    for (int i = idx; i < total; i += stride) {
        int c = (i & 63) * 4;
        float4 h = h4[i];
        float4 o = o4[i];
        float4 sc = *(const float4*)&ssc[c];
        float4 sh = *(const float4*)&ssh[c];
        o4[i] = make_float4(fmaf(h.x, sc.x, sh.x) + o.x,
                            fmaf(h.y, sc.y, sh.y) + o.y,
                            fmaf(h.z, sc.z, sh.z) + o.z,
                            fmaf(h.w, sc.w, sh.w) + o.w);
    }
}

// ---------------------------------------------------------------------------
extern "C" void kernel_launch(void* const* d_in, const int* in_sizes, int n_in,
                              void* d_out, int out_size) {
    const float* x      = (const float*)d_in[0];
    const int*   ei     = (const int*)d_in[1];
    const float* ea     = (const float*)d_in[2];
    const float* W_edge = (const float*)d_in[3];
    const float* W_rel  = (const float*)d_in[4];
    const float* b_rel  = (const float*)d_in[5];
    const float* W_root = (const float*)d_in[6];
    const float* gamma  = (const float*)d_in[7];
    const float* beta   = (const float*)d_in[8];
    const float* W_res  = (const float*)d_in[9];
    int E = in_sizes[1] / 2;
    float* out = (float*)d_out;

    const int EGEMM_SMEM = 98304 + 2048 + 1024;
    const int NODE_SMEM = 65536 + 1024;
    cudaFuncSetAttribute(egemm_fused, cudaFuncAttributeMaxDynamicSharedMemorySize, EGEMM_SMEM);
    cudaFuncSetAttribute(node_mma, cudaFuncAttributeMaxDynamicSharedMemorySize, NODE_SMEM);

    int nh = (E + 255) / 256;
    hist_prep<<<nh + 256 + 1184, 256>>>(ei, W_edge, W_rel, W_root, W_res, x, E, nh);  // 1
    scan_kernel<<<1, 1024>>>(E);                                                      // 2
    fill_kernel<<<nh, 256>>>(ei, E);                                                  // 3
    egemm_fused<<<(E + 127) / 128, 512, EGEMM_SMEM>>>(ea, x, E);                      // 4 (profiled)
    agg_split<<<1280, 256>>>();                                                       // 5
    dim3 gn((NNODES + 127) / 128, 4);
    node_mma<<<gn, 256, NODE_SMEM>>>(b_rel, out);                                     // 6
    finalize<<<592, 256>>>(gamma, beta, out);                                         // 7
}

// round 12
// speedup vs baseline: 1.2585x; 1.1512x over previous
#include <cuda_runtime.h>
#include <cuda_bf16.h>
#include <cstdint>

#define NNODES 20000
#define CH 256
#define ECH 64
#define MAXE 320000

typedef unsigned long long ull;

// ---------------- scratch (__device__ globals; no allocation) ----------------
__device__ float g_agg[NNODES * CH];          // fp32 aggregation target (self-cleaned)
__device__ float g_h[NNODES * CH];
__device__ int   g_cnt[NNODES];               // self-cleaned by scan
__device__ int   g_rowstart[NNODES + 1];
__device__ int   g_cursor[NNODES];
__device__ int4  g_csr4[MAXE];                // {eid, src, dst, 0}, dst-sorted
__device__ float g_sum[CH];                   // self-cleaned by agg_split
__device__ float g_sumsq[CH];
__device__ __align__(16) __nv_bfloat16 g_x_hi[NNODES * CH], g_x_lo[NNODES * CH];
__device__ __align__(16) __nv_bfloat16 g_agg_hi[NNODES * CH], g_agg_lo[NNODES * CH];
__device__ __align__(16) __nv_bfloat16 g_WTe_hi[CH * ECH], g_WTe_lo[CH * ECH];
__device__ __align__(16) __nv_bfloat16 g_WTrel_hi[CH * CH], g_WTrel_lo[CH * CH];
__device__ __align__(16) __nv_bfloat16 g_WTroot_hi[CH * CH], g_WTroot_lo[CH * CH];
__device__ __align__(16) __nv_bfloat16 g_WTres_hi[CH * CH], g_WTres_lo[CH * CH];

// ---------------- helpers ----------------
__device__ __forceinline__ uint32_t smem_u32(const void* p) {
    uint32_t a;
    asm("{ .reg .u64 t; cvta.to.shared.u64 t, %1; cvt.u32.u64 %0, t; }" : "=r"(a) : "l"(p));
    return a;
}
#define SWZ(off) ((off) ^ (((off) >> 3) & 0x70))

__device__ __forceinline__ void cpa16(uint32_t dst, const void* src, int pred16) {
    asm volatile("cp.async.cg.shared.global [%0], [%1], 16, %2;"
                 :: "r"(dst), "l"(src), "r"(pred16 ? 16 : 0) : "memory");
}
#define CP_COMMIT() asm volatile("cp.async.commit_group;" ::: "memory")
#define CP_WAIT(n)  asm volatile("cp.async.wait_group %0;" :: "n"(n) : "memory")

__device__ __forceinline__ void ldsm_x4(uint32_t* r, uint32_t addr) {
    asm volatile("ldmatrix.sync.aligned.m8n8.x4.shared.b16 {%0,%1,%2,%3}, [%4];"
        : "=r"(r[0]), "=r"(r[1]), "=r"(r[2]), "=r"(r[3]) : "r"(addr));
}
__device__ __forceinline__ void ldsm_x2(uint32_t* r, uint32_t addr) {
    asm volatile("ldmatrix.sync.aligned.m8n8.x2.shared.b16 {%0,%1}, [%2];"
        : "=r"(r[0]), "=r"(r[1]) : "r"(addr));
}
__device__ __forceinline__ void mma16816(float* c, const uint32_t* a, const uint32_t* b) {
    asm volatile("mma.sync.aligned.m16n8k16.row.col.f32.bf16.bf16.f32 "
        "{%0,%1,%2,%3}, {%4,%5,%6,%7}, {%8,%9}, {%0,%1,%2,%3};"
        : "+f"(c[0]), "+f"(c[1]), "+f"(c[2]), "+f"(c[3])
        : "r"(a[0]), "r"(a[1]), "r"(a[2]), "r"(a[3]), "r"(b[0]), "r"(b[1]));
}
__device__ __forceinline__ void split4(float4 v, ull& hb, ull& lb) {
    __nv_bfloat16 h0 = __float2bfloat16(v.x), h1 = __float2bfloat16(v.y);
    __nv_bfloat16 h2 = __float2bfloat16(v.z), h3 = __float2bfloat16(v.w);
    __nv_bfloat16 l0 = __float2bfloat16(v.x - __bfloat162float(h0));
    __nv_bfloat16 l1 = __float2bfloat16(v.y - __bfloat162float(h1));
    __nv_bfloat16 l2 = __float2bfloat16(v.z - __bfloat162float(h2));
    __nv_bfloat16 l3 = __float2bfloat16(v.w - __bfloat162float(h3));
    hb = (ull)__bfloat16_as_ushort(h0) | ((ull)__bfloat16_as_ushort(h1) << 16) |
         ((ull)__bfloat16_as_ushort(h2) << 32) | ((ull)__bfloat16_as_ushort(h3) << 48);
    lb = (ull)__bfloat16_as_ushort(l0) | ((ull)__bfloat16_as_ushort(l1) << 16) |
         ((ull)__bfloat16_as_ushort(l2) << 32) | ((ull)__bfloat16_as_ushort(l3) << 48);
}

// ---------------------------------------------------------------------------
// K1: hist + weight prep + x split (disjoint block ranges)
// ---------------------------------------------------------------------------
__global__ void __launch_bounds__(256) hist_prep(
    const int* __restrict__ ei,
    const float* __restrict__ We, const float* __restrict__ Wrel,
    const float* __restrict__ Wroot, const float* __restrict__ Wres,
    const float* __restrict__ x, int E, int nh)
{
    int b = blockIdx.x;
    int t = threadIdx.x;
    if (b < nh) {
        int e = b * 256 + t;
        if (e < E) atomicAdd(&g_cnt[__ldg(&ei[E + e])], 1);
    } else if (b < nh + 256) {
        int n = b - nh, k = t;
        if (k < ECH) {
            float v = __ldg(&We[(size_t)k * CH + n]);
            __nv_bfloat16 h = __float2bfloat16(v);
            g_WTe_hi[n * ECH + k] = h;
            g_WTe_lo[n * ECH + k] = __float2bfloat16(v - __bfloat162float(h));
        }
        {
            float v = __ldg(&Wrel[(size_t)k * CH + n]);
            __nv_bfloat16 h = __float2bfloat16(v);
            g_WTrel_hi[n * CH + k] = h;
            g_WTrel_lo[n * CH + k] = __float2bfloat16(v - __bfloat162float(h));
        }
        {
            float v = __ldg(&Wroot[(size_t)k * CH + n]);
            __nv_bfloat16 h = __float2bfloat16(v);
            g_WTroot_hi[n * CH + k] = h;
            g_WTroot_lo[n * CH + k] = __float2bfloat16(v - __bfloat162float(h));
        }
        {
            float v = __ldg(&Wres[(size_t)k * CH + n]);
            __nv_bfloat16 h = __float2bfloat16(v);
            g_WTres_hi[n * CH + k] = h;
            g_WTres_lo[n * CH + k] = __float2bfloat16(v - __bfloat162float(h));
        }
    } else {
        const int total = NNODES * CH / 4;
        int idx = (b - nh - 256) * 256 + t;
        int stride = (gridDim.x - nh - 256) * 256;
        for (int i = idx; i < total; i += stride) {
            float4 v = __ldg(((const float4*)x) + i);
            ull hb, lb; split4(v, hb, lb);
            ((ull*)g_x_hi)[i] = hb;
            ((ull*)g_x_lo)[i] = lb;
        }
    }
}

// ---------------------------------------------------------------------------
// K2: scan (reads g_cnt, zeroes it for the next replay)
// ---------------------------------------------------------------------------
__global__ void __launch_bounds__(1024) scan_kernel(int E) {
    __shared__ int sp[1024];
    const int t = threadIdx.x;
    const int CHUNK = (NNODES + 1023) / 1024;
    int beg = t * CHUNK;
    int end = min(beg + CHUNK, NNODES);
    int mysum = 0;
    for (int i = beg; i < end; i++) mysum += g_cnt[i];
    sp[t] = mysum;
    __syncthreads();
#pragma unroll
    for (int off = 1; off < 1024; off <<= 1) {
        int v = (t >= off) ? sp[t - off] : 0;
        __syncthreads();
        sp[t] += v;
        __syncthreads();
    }
    int running = sp[t] - mysum;
    for (int i = beg; i < end; i++) {
        int c = g_cnt[i];
        g_cnt[i] = 0;               // self-clean for next replay
        g_rowstart[i] = running;
        g_cursor[i] = running;
        running += c;
    }
    if (t == 1023) g_rowstart[NNODES] = E;
}

// ---------------------------------------------------------------------------
// K3: fill CSR as int4 {eid, src, dst, 0}
// ---------------------------------------------------------------------------
__global__ void fill_kernel(const int* __restrict__ ei, int E) {
    int e = blockIdx.x * blockDim.x + threadIdx.x;
    if (e < E) {
        int dst = __ldg(&ei[E + e]);
        int src = __ldg(&ei[e]);
        int pos = atomicAdd(&g_cursor[dst], 1);
        g_csr4[pos] = make_int4(e, src, dst, 0);
    }
}

// ---------------------------------------------------------------------------
// K4 (profiled): fused edge GEMM + message + aggregation (R8 base).
// Epilogue change vs R8: the 4 x-row float2 loads per (i,half) are issued
// BEFORE the shfl/RED chains (volatile RED was fencing them to MLP=1).
// smem: Ah 16K | Al 16K | Bh 32K | Bl 32K | csr 2K
// ---------------------------------------------------------------------------
__global__ void __launch_bounds__(512, 2) egemm_fused(
    const float* __restrict__ ea, const float* __restrict__ x, int E)
{
    extern __shared__ char dsm[];
    char* base = (char*)(((uintptr_t)dsm + 1023) & ~(uintptr_t)1023);
    char* Ah = base;
    char* Al = base + 16384;
    char* Bh = base + 32768;
    char* Bl = base + 65536;
    int4* s_csr = (int4*)(base + 98304);

    const int tid = threadIdx.x;
    const int lane = tid & 31;
    const int wid = tid >> 5;
    const int wm = wid >> 3;     // 0..1
    const int wn = wid & 7;      // 0..7
    const int m0 = blockIdx.x * 128;

    // stage CSR tile
    if (tid < 128) {
        int r = m0 + tid;
        s_csr[tid] = (r < E) ? __ldg(&g_csr4[r]) : make_int4(0, 0, -1, 0);
    }
    __syncthreads();

    // A: gather ea rows in CSR order, split fp32 -> hi/lo bf16
    for (int idx = tid; idx < 2048; idx += 512) {
        int row = idx >> 4, q = idx & 15;
        int4 cs = s_csr[row];
        float4 v = make_float4(0.f, 0.f, 0.f, 0.f);
        if (cs.z >= 0) v = __ldg((const float4*)(ea + (size_t)cs.x * ECH) + q);
        ull hb, lb; split4(v, hb, lb);
        uint32_t off = SWZ(row * 128 + q * 8);
        *(ull*)(Ah + off) = hb;
        *(ull*)(Al + off) = lb;
    }
    // B: WTe 256 x 64 bf16 hi/lo
    {
        const uint4* sh = (const uint4*)g_WTe_hi;
        const uint4* sl = (const uint4*)g_WTe_lo;
        for (int idx = tid; idx < 2048; idx += 512) {
            int n = idx >> 3, q = idx & 7;
            uint32_t off = SWZ(n * 128 + q * 16);
            *(uint4*)(Bh + off) = __ldg(&sh[idx]);
            *(uint4*)(Bl + off) = __ldg(&sl[idx]);
        }
    }
    __syncthreads();

    float acc[4][4][4];
#pragma unroll
    for (int i = 0; i < 4; i++)
#pragma unroll
        for (int j = 0; j < 4; j++)
#pragma unroll
            for (int k = 0; k < 4; k++) acc[i][j][k] = 0.f;

    const uint32_t ah = smem_u32(Ah), al = smem_u32(Al);
    const uint32_t bh = smem_u32(Bh), bl = smem_u32(Bl);

#pragma unroll
    for (int ks = 0; ks < 4; ks++) {
        int ko = ks * 32;
        uint32_t afh[4][4], afl[4][4];
#pragma unroll
        for (int i = 0; i < 4; i++) {
            uint32_t aoff = SWZ((wm * 64 + i * 16 + (lane & 15)) * 128 + ko + (lane >> 4) * 16);
            ldsm_x4(afh[i], ah + aoff);
            ldsm_x4(afl[i], al + aoff);
        }
#pragma unroll
        for (int j = 0; j < 4; j++) {
            uint32_t boff = SWZ((wn * 32 + j * 8 + (lane & 7)) * 128 + ko + ((lane >> 3) & 1) * 16);
            uint32_t bfh[2], bfl[2];
            ldsm_x2(bfh, bh + boff);
            ldsm_x2(bfl, bl + boff);
#pragma unroll
            for (int i = 0; i < 4; i++) {
                mma16816(acc[i][j], afh[i], bfh);
                mma16816(acc[i][j], afh[i], bfl);
                mma16816(acc[i][j], afl[i], bfh);
            }
        }
    }

    // fused epilogue: multiply by x[src], shfl segment-reduce, RED.
    // x loads for all 4 j-tiles are issued before the dependent chain (MLP=4).
#pragma unroll
    for (int i = 0; i < 4; i++) {
#pragma unroll
        for (int half = 0; half < 2; half++) {
            const int g = lane >> 2, tig = lane & 3;
            int rr = wm * 64 + i * 16 + half * 8 + g;
            int4 cs = s_csr[rr];
            int d = cs.z;
            const float* xr = x + (size_t)cs.y * CH;
            // prefetch all 4 x float2s first (independent LDGs in flight)
            float2 xv[4];
#pragma unroll
            for (int j = 0; j < 4; j++)
                xv[j] = __ldg((const float2*)(xr + wn * 32 + j * 8 + 2 * tig));

            int dprev = __shfl_up_sync(0xFFFFFFFFu, d, 4);
            bool head = (g == 0) || (dprev != d);
            int dn4 = __shfl_down_sync(0xFFFFFFFFu, d, 4);
            int dn8 = __shfl_down_sync(0xFFFFFFFFu, d, 8);
            int dn16 = __shfl_down_sync(0xFFFFFFFFu, d, 16);
            bool m4 = (g < 7) && (dn4 == d);
            bool m8 = (g < 6) && (dn8 == d);
            bool m16 = (g < 4) && (dn16 == d);
            float* arow = g_agg + (size_t)(d < 0 ? 0 : d) * CH;
#pragma unroll
            for (int j = 0; j < 4; j++) {
                int c = wn * 32 + j * 8 + 2 * tig;
                float vx = (half ? acc[i][j][2] : acc[i][j][0]) * xv[j].x;
                float vy = (half ? acc[i][j][3] : acc[i][j][1]) * xv[j].y;
                float t;
                t = __shfl_down_sync(0xFFFFFFFFu, vx, 4);  vx += m4 ? t : 0.f;
                t = __shfl_down_sync(0xFFFFFFFFu, vy, 4);  vy += m4 ? t : 0.f;
                t = __shfl_down_sync(0xFFFFFFFFu, vx, 8);  vx += m8 ? t : 0.f;
                t = __shfl_down_sync(0xFFFFFFFFu, vy, 8);  vy += m8 ? t : 0.f;
                t = __shfl_down_sync(0xFFFFFFFFu, vx, 16); vx += m16 ? t : 0.f;
                t = __shfl_down_sync(0xFFFFFFFFu, vy, 16); vy += m16 ? t : 0.f;
                if (head && d >= 0) {
                    asm volatile("red.global.add.v2.f32 [%0], {%1, %2};"
                                 :: "l"(arow + c), "f"(vx), "f"(vy) : "memory");
                }
            }
        }
    }
}

// ---------------------------------------------------------------------------
// K5: agg fp32 -> bf16 hi/lo; self-clean g_agg and g_sum/g_sumsq
// ---------------------------------------------------------------------------
__global__ void __launch_bounds__(256) agg_split() {
    int gid = blockIdx.x * blockDim.x + threadIdx.x;
    int stride = gridDim.x * blockDim.x;
    const int total = NNODES * CH / 4;
    float4* a4 = (float4*)g_agg;
    for (int i = gid; i < total; i += stride) {
        float4 v = a4[i];
        ull hb, lb; split4(v, hb, lb);
        ((ull*)g_agg_hi)[i] = hb;
        ((ull*)g_agg_lo)[i] = lb;
        a4[i] = make_float4(0.f, 0.f, 0.f, 0.f);
    }
    if (gid < CH) { g_sum[gid] = 0.f; g_sumsq[gid] = 0.f; }
}

// ---------------------------------------------------------------------------
// K6: node MMA (R8-proven). grid (157, 4), 256 thr, tile 128x128, dbl buffer.
// smem: 2 x (Ah 16K | Al 16K | Bh 16K | Bl 16K) = 128KB
// ---------------------------------------------------------------------------
__global__ void __launch_bounds__(256) node_mma(
    const float* __restrict__ b_rel, float* __restrict__ out)
{
    extern __shared__ char dsm[];
    char* base = (char*)(((uintptr_t)dsm + 1023) & ~(uintptr_t)1023);

    const int tid = threadIdx.x;
    const int lane = tid & 31;
    const int wid = tid >> 5;
    const int wm = wid >> 2;
    const int wn = wid & 3;
    const int m0 = blockIdx.x * 128;
    const int yb = blockIdx.y;
    const bool isH = (yb < 2);
    const int n0 = (isH ? yb : yb - 2) * 128;

    const __nv_bfloat16* Asrc_hi[2];
    const __nv_bfloat16* Asrc_lo[2];
    const __nv_bfloat16* Bsrc_hi[2];
    const __nv_bfloat16* Bsrc_lo[2];
    int nsrc;
    if (isH) {
        nsrc = 2;
        Asrc_hi[0] = g_agg_hi; Asrc_lo[0] = g_agg_lo;
        Bsrc_hi[0] = g_WTrel_hi; Bsrc_lo[0] = g_WTrel_lo;
        Asrc_hi[1] = g_x_hi; Asrc_lo[1] = g_x_lo;
        Bsrc_hi[1] = g_WTroot_hi; Bsrc_lo[1] = g_WTroot_lo;
    } else {
        nsrc = 1;
        Asrc_hi[0] = g_x_hi; Asrc_lo[0] = g_x_lo;
        Bsrc_hi[0] = g_WTres_hi; Bsrc_lo[0] = g_WTres_lo;
    }
    const int np = nsrc * 4;

    auto prefetch = [&](int p, int b) {
        int s = p >> 2, kc = p & 3;
        int k0b = kc * 128;
        char* Ah = base + b * 65536;
        char* Al = Ah + 16384;
        char* Bh = Ah + 32768;
        char* Bl = Ah + 49152;
        const char* ahp = (const char*)Asrc_hi[s];
        const char* alp = (const char*)Asrc_lo[s];
        const char* bhp = (const char*)Bsrc_hi[s];
        const char* blp = (const char*)Bsrc_lo[s];
        for (int idx = tid; idx < 1024; idx += 256) {
            int row = idx >> 3, q = idx & 7;
            int r = m0 + row;
            int ok = (r < NNODES);
            int rr = ok ? r : 0;
            uint32_t off = SWZ(row * 128 + q * 16);
            cpa16(smem_u32(Ah) + off, ahp + (size_t)rr * 512 + k0b + q * 16, ok);
            cpa16(smem_u32(Al) + off, alp + (size_t)rr * 512 + k0b + q * 16, ok);
        }
        for (int idx = tid; idx < 1024; idx += 256) {
            int n = idx >> 3, q = idx & 7;
            uint32_t off = SWZ(n * 128 + q * 16);
            cpa16(smem_u32(Bh) + off, bhp + (size_t)(n0 + n) * 512 + k0b + q * 16, 1);
            cpa16(smem_u32(Bl) + off, blp + (size_t)(n0 + n) * 512 + k0b + q * 16, 1);
        }
        CP_COMMIT();
    };

    float acc[4][4][4];
#pragma unroll
    for (int i = 0; i < 4; i++)
#pragma unroll
        for (int j = 0; j < 4; j++)
#pragma unroll
            for (int k = 0; k < 4; k++) acc[i][j][k] = 0.f;

    prefetch(0, 0);
    for (int p = 0; p < np; p++) {
        if (p + 1 < np) {
            prefetch(p + 1, (p + 1) & 1);
            CP_WAIT(1);
        } else {
            CP_WAIT(0);
        }
        __syncthreads();
        char* Ab = base + (p & 1) * 65536;
        const uint32_t ah = smem_u32(Ab), al = ah + 16384;
        const uint32_t bh = ah + 32768, bl = ah + 49152;
#pragma unroll
        for (int ks = 0; ks < 4; ks++) {
            int ko = ks * 32;
            uint32_t afh[4][4], afl[4][4];
#pragma unroll
            for (int i = 0; i < 4; i++) {
                uint32_t aoff = SWZ((wm * 64 + i * 16 + (lane & 15)) * 128 + ko + (lane >> 4) * 16);
                ldsm_x4(afh[i], ah + aoff);
                ldsm_x4(afl[i], al + aoff);
            }
#pragma unroll
            for (int j = 0; j < 4; j++) {
                uint32_t boff = SWZ((wn * 32 + j * 8 + (lane & 7)) * 128 + ko + ((lane >> 3) & 1) * 16);
                uint32_t bfh[2], bfl[2];
                ldsm_x2(bfh, bh + boff);
                ldsm_x2(bfl, bl + boff);
#pragma unroll
                for (int i = 0; i < 4; i++) {
                    mma16816(acc[i][j], afh[i], bfh);
                    mma16816(acc[i][j], afh[i], bfl);
                    mma16816(acc[i][j], afl[i], bfh);
                }
            }
        }
        __syncthreads();
    }

    const int g = lane >> 2, tig = lane & 3;
    if (isH) {
        float cs[4][2], cq[4][2];
#pragma unroll
        for (int j = 0; j < 4; j++) { cs[j][0] = cs[j][1] = cq[j][0] = cq[j][1] = 0.f; }
#pragma unroll
        for (int j = 0; j < 4; j++) {
            int c = n0 + wn * 32 + j * 8 + 2 * tig;
            float2 b = *(const float2*)(b_rel + c);
#pragma unroll
            for (int i = 0; i < 4; i++) {
                int r0 = m0 + wm * 64 + i * 16 + g;
                if (r0 < NNODES) {
                    float v0 = fmaxf(acc[i][j][0] + b.x, 0.f);
                    float v1 = fmaxf(acc[i][j][1] + b.y, 0.f);
                    *(float2*)(g_h + (size_t)r0 * CH + c) = make_float2(v0, v1);
                    cs[j][0] += v0; cs[j][1] += v1;
                    cq[j][0] += v0 * v0; cq[j][1] += v1 * v1;
                }
                if (r0 + 8 < NNODES) {
                    float v0 = fmaxf(acc[i][j][2] + b.x, 0.f);
                    float v1 = fmaxf(acc[i][j][3] + b.y, 0.f);
                    *(float2*)(g_h + (size_t)(r0 + 8) * CH + c) = make_float2(v0, v1);
                    cs[j][0] += v0; cs[j][1] += v1;
                    cq[j][0] += v0 * v0; cq[j][1] += v1 * v1;
                }
            }
        }
#pragma unroll
        for (int j = 0; j < 4; j++)
#pragma unroll
            for (int t2 = 0; t2 < 2; t2++) {
#pragma unroll
                for (int m = 4; m <= 16; m <<= 1) {
                    cs[j][t2] += __shfl_xor_sync(0xFFFFFFFF, cs[j][t2], m);
                    cq[j][t2] += __shfl_xor_sync(0xFFFFFFFF, cq[j][t2], m);
                }
            }
        if (lane < 4) {
#pragma unroll
            for (int j = 0; j < 4; j++) {
                int c = n0 + wn * 32 + j * 8 + 2 * lane;
                atomicAdd(&g_sum[c], cs[j][0]);
                atomicAdd(&g_sum[c + 1], cs[j][1]);
                atomicAdd(&g_sumsq[c], cq[j][0]);
                atomicAdd(&g_sumsq[c + 1], cq[j][1]);
            }
        }
    } else {
#pragma unroll
        for (int j = 0; j < 4; j++) {
            int c = n0 + wn * 32 + j * 8 + 2 * tig;
#pragma unroll
            for (int i = 0; i < 4; i++) {
                int r0 = m0 + wm * 64 + i * 16 + g;
                if (r0 < NNODES)
                    *(float2*)(out + (size_t)r0 * CH + c) = make_float2(acc[i][j][0], acc[i][j][1]);
                if (r0 + 8 < NNODES)
                    *(float2*)(out + (size_t)(r0 + 8) * CH + c) = make_float2(acc[i][j][2], acc[i][j][3]);
            }
        }
    }
}

// ---------------------------------------------------------------------------
// K7: finalize
// ---------------------------------------------------------------------------
__global__ void __launch_bounds__(256) finalize(
    const float* __restrict__ gamma, const float* __restrict__ beta,
    float* __restrict__ out)
{
    __shared__ float ssc[CH], ssh[CH];
    int t = threadIdx.x;
    {
        float m = g_sum[t] * (1.0f / NNODES);
        float var = g_sumsq[t] * (1.0f / NNODES) - m * m;
        float is = rsqrtf(var + 1e-5f);
        float sc = is * __ldg(&gamma[t]);
        ssc[t] = sc;
        ssh[t] = __ldg(&beta[t]) - m * sc;
    }
    __syncthreads();
    int idx = blockIdx.x * blockDim.x + t;
    int stride = gridDim.x * blockDim.x;
    const int total = NNODES * CH / 4;
    const float4* h4 = (const float4*)g_h;
    float4* o4 = (float4*)out;
    for (int i = idx; i < total; i += stride) {
        int c = (i & 63) * 4;
        float4 h = h4[i];
        float4 o = o4[i];
        float4 sc = *(const float4*)&ssc[c];
        float4 sh = *(const float4*)&ssh[c];
        o4[i] = make_float4(fmaf(h.x, sc.x, sh.x) + o.x,
                            fmaf(h.y, sc.y, sh.y) + o.y,
                            fmaf(h.z, sc.z, sh.z) + o.z,
                            fmaf(h.w, sc.w, sh.w) + o.w);
    }
}

// ---------------------------------------------------------------------------
extern "C" void kernel_launch(void* const* d_in, const int* in_sizes, int n_in,
                              void* d_out, int out_size) {
    const float* x      = (const float*)d_in[0];
    const int*   ei     = (const int*)d_in[1];
    const float* ea     = (const float*)d_in[2];
    const float* W_edge = (const float*)d_in[3];
    const float* W_rel  = (const float*)d_in[4];
    const float* b_rel  = (const float*)d_in[5];
    const float* W_root = (const float*)d_in[6];
    const float* gamma  = (const float*)d_in[7];
    const float* beta   = (const float*)d_in[8];
    const float* W_res  = (const float*)d_in[9];
    int E = in_sizes[1] / 2;
    float* out = (float*)d_out;

    const int EGEMM_SMEM = 98304 + 2048 + 1024;
    const int NODE_SMEM = 131072 + 1024;
    cudaFuncSetAttribute(egemm_fused, cudaFuncAttributeMaxDynamicSharedMemorySize, EGEMM_SMEM);
    cudaFuncSetAttribute(node_mma, cudaFuncAttributeMaxDynamicSharedMemorySize, NODE_SMEM);

    int nh = (E + 255) / 256;
    hist_prep<<<nh + 256 + 1184, 256>>>(ei, W_edge, W_rel, W_root, W_res, x, E, nh);  // 1
    scan_kernel<<<1, 1024>>>(E);                                                      // 2
    fill_kernel<<<nh, 256>>>(ei, E);                                                  // 3
    egemm_fused<<<(E + 127) / 128, 512, EGEMM_SMEM>>>(ea, x, E);                      // 4 (profiled)
    agg_split<<<1280, 256>>>();                                                       // 5
    dim3 gn((NNODES + 127) / 128, 4);
    node_mma<<<gn, 256, NODE_SMEM>>>(b_rel, out);                                     // 6
    finalize<<<592, 256>>>(gamma, beta, out);                                         // 7
}